// round 5
// baseline (speedup 1.0000x reference)
#include <cuda_runtime.h>
#include <cuda_bf16.h>
#include <cstdint>

#define BB 8
#define CC 64
#define HH 128
#define WW 128
#define HWP (HH*WW)
#define K2 9
#define OFFC 18
#define MASKC 9
#define NOUT 27
#define NOUTP 28

// ---------------------------------------------------------------------------
// Device scratch (graph-safe)
// ---------------------------------------------------------------------------
__device__ float g_offset[BB * OFFC * HWP];
__device__ float g_mask  [BB * MASKC * HWP];
__device__ float g_xt    [(size_t)BB * HWP * CC];   // x in NHWC (33.5 MB)
// W in mma-fragment order: [tap][hi/lo][nn(8)][kk(4)][lane(32)] x uint2
__device__ __align__(16) uint2 g_wfrag[K2 * 2 * 8 * 4 * 32];

__device__ __forceinline__ uint32_t smem_u32(const void* p) {
    uint32_t a;
    asm("{ .reg .u64 t; cvta.to.shared.u64 t, %1; cvt.u32.u64 %0, t; }" : "=r"(a) : "l"(p));
    return a;
}

__device__ __forceinline__ void ldm_x4(uint32_t* r, uint32_t addr) {
    asm volatile("ldmatrix.sync.aligned.m8n8.x4.shared.b16 {%0,%1,%2,%3}, [%4];"
        : "=r"(r[0]), "=r"(r[1]), "=r"(r[2]), "=r"(r[3]) : "r"(addr));
}

__device__ __forceinline__ void mma16816(float* d, const uint32_t* a, const uint32_t* b) {
    asm volatile(
        "mma.sync.aligned.m16n8k16.row.col.f32.bf16.bf16.f32 "
        "{%0,%1,%2,%3}, {%4,%5,%6,%7}, {%8,%9}, {%0,%1,%2,%3};"
        : "+f"(d[0]), "+f"(d[1]), "+f"(d[2]), "+f"(d[3])
        : "r"(a[0]), "r"(a[1]), "r"(a[2]), "r"(a[3]), "r"(b[0]), "r"(b[1]));
}

// ---------------------------------------------------------------------------
// NCHW -> NHWC transpose via smem tiles
// ---------------------------------------------------------------------------
__global__ __launch_bounds__(256) void nhwc_kernel(const float* __restrict__ x)
{
    __shared__ float tile[32][33];
    const int b  = blockIdx.z;
    const int c0 = blockIdx.y * 32;
    const int p0 = blockIdx.x * 32;
    const int tx = threadIdx.x, ty = threadIdx.y;

#pragma unroll
    for (int i = 0; i < 4; i++)
        tile[ty + 8 * i][tx] = x[((size_t)b * CC + c0 + ty + 8 * i) * HWP + p0 + tx];
    __syncthreads();
#pragma unroll
    for (int i = 0; i < 4; i++)
        g_xt[((size_t)b * HWP + p0 + ty + 8 * i) * CC + c0 + tx] = tile[tx][ty + 8 * i];
}

// ---------------------------------------------------------------------------
// Setup: w_conv [co][c][k] -> fragment-ordered bf16 hi/lo tiles (unchanged)
// ---------------------------------------------------------------------------
__global__ void wfrag_kernel(const float* __restrict__ w_conv)
{
    int i = blockIdx.x * 256 + threadIdx.x;
    if (i >= K2 * 2 * 8 * 4 * 32) return;
    int lane = i & 31;
    int kk   = (i >> 5) & 3;
    int nn   = (i >> 7) & 7;
    int hl   = (i >> 10) & 1;
    int k    = i >> 11;

    int co    = nn * 8 + (lane >> 2);
    int cbase = kk * 16 + 2 * (lane & 3);

    uint32_t regs[2];
#pragma unroll
    for (int r = 0; r < 2; r++) {
        uint32_t pk = 0;
#pragma unroll
        for (int j = 0; j < 2; j++) {
            int c = cbase + r * 8 + j;
            float wv = w_conv[(co * CC + c) * K2 + k];
            __nv_bfloat16 hi = __float2bfloat16(wv);
            float lov = wv - __bfloat162float(hi);
            __nv_bfloat16 v = hl ? __float2bfloat16(lov) : hi;
            pk |= ((uint32_t)__bfloat16_as_ushort(v)) << (16 * j);
        }
        regs[r] = pk;
    }
    g_wfrag[i] = make_uint2(regs[0], regs[1]);
}

// ---------------------------------------------------------------------------
// Kernel 1: offset/mask conv, NHWC reads (float4), weights staged per chunk
// ---------------------------------------------------------------------------
__global__ __launch_bounds__(128) void offmask_kernel(
    const float* __restrict__ w_off,
    const float* __restrict__ w_msk)
{
    const int w = threadIdx.x;
    const int h = blockIdx.x;
    const int b = blockIdx.y;

    __shared__ float ws[K2 * 16 * NOUTP];   // [tap][cc(16)][co(28)] = 16 KB

    float acc[NOUTP];
#pragma unroll
    for (int i = 0; i < NOUTP; i++) acc[i] = 0.f;

    // per-tap source pixel + validity
    int   pix_t[K2];
    bool  ok_t[K2];
#pragma unroll
    for (int tap = 0; tap < K2; tap++) {
        int yy = h + tap / 3 - 1;
        int xx = w + tap % 3 - 1;
        bool ok = (yy >= 0) && (yy < HH) && (xx >= 0) && (xx < WW);
        ok_t[tap]  = ok;
        pix_t[tap] = ok ? (yy * WW + xx) : 0;
    }

    const float* xb = g_xt + (size_t)b * HWP * CC;

#pragma unroll 1
    for (int c0 = 0; c0 < CC; c0 += 16) {
        __syncthreads();
        for (int i = threadIdx.x; i < K2 * 16 * NOUTP; i += 128) {
            int co  = i % NOUTP;
            int r   = i / NOUTP;
            int cc  = r % 16;
            int tap = r / 16;
            int c   = c0 + cc;
            float v = 0.f;
            if (co < OFFC)      v = w_off[(co * CC + c) * 9 + tap];
            else if (co < NOUT) v = w_msk[((co - OFFC) * CC + c) * 9 + tap];
            ws[i] = v;
        }
        __syncthreads();

#pragma unroll 1
        for (int tap = 0; tap < K2; tap++) {
            if (!ok_t[tap]) continue;
            const float* p = xb + (size_t)pix_t[tap] * CC + c0;
#pragma unroll
            for (int q4 = 0; q4 < 4; q4++) {
                float4 xv = *(const float4*)(p + 4 * q4);
                const float* wr = ws + (tap * 16 + q4 * 4) * NOUTP;
#pragma unroll
                for (int j = 0; j < 4; j++) {
                    float v = (j == 0) ? xv.x : (j == 1) ? xv.y : (j == 2) ? xv.z : xv.w;
                    const float4* wv4 = (const float4*)(wr + j * NOUTP);
#pragma unroll
                    for (int q = 0; q < 7; q++) {
                        float4 wv = wv4[q];
                        acc[4 * q + 0] = fmaf(wv.x, v, acc[4 * q + 0]);
                        acc[4 * q + 1] = fmaf(wv.y, v, acc[4 * q + 1]);
                        acc[4 * q + 2] = fmaf(wv.z, v, acc[4 * q + 2]);
                        acc[4 * q + 3] = fmaf(wv.w, v, acc[4 * q + 3]);
                    }
                }
            }
        }
    }

    const int pix = h * WW + w;
#pragma unroll
    for (int co = 0; co < OFFC; co++)
        g_offset[(b * OFFC + co) * HWP + pix] = acc[co];
#pragma unroll
    for (int cm = 0; cm < MASKC; cm++) {
        float v = acc[OFFC + cm];
        g_mask[(b * MASKC + cm) * HWP + pix] = 1.f / (1.f + __expf(-v));
    }
}

// ---------------------------------------------------------------------------
// Kernel 2: deform via mma.sync; gather now vectorized from NHWC g_xt
// ---------------------------------------------------------------------------
#define SMEM_BYTES (16384 * 3 + 1024)

__global__ __launch_bounds__(128) void deform_kernel(float* __restrict__ out)
{
    extern __shared__ char smraw[];
    const uint32_t raw_u  = smem_u32(smraw);
    const uint32_t base_u = (raw_u + 1023) & ~1023u;
    char* const smb = smraw + (base_u - raw_u);

    const uint32_t uAhi = base_u;            // 16 KB: [128 pix][64 c] bf16, SW128
    const uint32_t uAlo = base_u + 16384;    // 16 KB
    char* const sWf = smb + 32768;           // 16 KB: fragment-ordered W (hi+lo)

    const int t    = threadIdx.x;
    const int lane = t & 31;
    const int wrp  = t >> 5;
    const int h    = blockIdx.x;
    const int b    = blockIdx.y;

    float acc[64];   // [mt(2)][nn(8)][q(4)]
#pragma unroll
    for (int i = 0; i < 64; i++) acc[i] = 0.f;

    const float* xb = g_xt + (size_t)b * HWP * CC;

    uint32_t lda[2][4];
#pragma unroll
    for (int mt = 0; mt < 2; mt++) {
        int r = wrp * 32 + mt * 16 + (lane & 15);
#pragma unroll
        for (int kk = 0; kk < 4; kk++) {
            int chunk = kk * 2 + (lane >> 4);
            lda[mt][kk] = (uint32_t)(r * 128 + ((chunk ^ (r & 7)) * 16));
        }
    }

#pragma unroll 1
    for (int k = 0; k < K2; k++) {
        __syncthreads();   // previous tap's mma reads done

        // ---- stage W fragments for this tap (16 KB) ----
        {
            const uint4* src = (const uint4*)(g_wfrag + (size_t)k * 2048);
            uint4* dst = (uint4*)sWf;
#pragma unroll
            for (int i = 0; i < 8; i++)
                dst[t + 128 * i] = src[t + 128 * i];
        }

        // ---- bilinear params for this thread's pixel ----
        const int w   = t;
        const int pix = h * WW + w;
        float offy = g_offset[(b * OFFC + 2 * k    ) * HWP + pix];
        float offx = g_offset[(b * OFFC + 2 * k + 1) * HWP + pix];
        float m    = g_mask  [(b * MASKC + k       ) * HWP + pix];

        const int ki = k / 3, kj = k % 3;
        float py = (float)(h + ki - 1) + offy;
        float px = (float)(w + kj - 1) + offx;
        float y0f = floorf(py), x0f = floorf(px);
        int   y0 = (int)y0f,    x0 = (int)x0f;
        int   y1 = y0 + 1,      x1 = x0 + 1;
        float wy1 = py - y0f,   wx1 = px - x0f;
        float wy0 = 1.f - wy1,  wx0 = 1.f - wx1;

        bool vy0 = (y0 >= 0) && (y0 < HH), vy1 = (y1 >= 0) && (y1 < HH);
        bool vx0 = (x0 >= 0) && (x0 < WW), vx1 = (x1 >= 0) && (x1 < WW);

        float w00 = (vy0 && vx0) ? wy0 * wx0 * m : 0.f;
        float w01 = (vy0 && vx1) ? wy0 * wx1 * m : 0.f;
        float w10 = (vy1 && vx0) ? wy1 * wx0 * m : 0.f;
        float w11 = (vy1 && vx1) ? wy1 * wx1 * m : 0.f;

        int yc0 = min(max(y0, 0), HH - 1), yc1 = min(max(y1, 0), HH - 1);
        int xc0 = min(max(x0, 0), WW - 1), xc1 = min(max(x1, 0), WW - 1);

        const float* p00 = xb + (size_t)(yc0 * WW + xc0) * CC;
        const float* p01 = xb + (size_t)(yc0 * WW + xc1) * CC;
        const float* p10 = xb + (size_t)(yc1 * WW + xc0) * CC;
        const float* p11 = xb + (size_t)(yc1 * WW + xc1) * CC;

        // ---- sample 64 channels (vectorized), split hi/lo, store swizzled ----
#pragma unroll 1
        for (int cc = 0; cc < 8; cc++) {
            const int c0 = cc * 8;
            uint32_t Hq[4], Lq[4];
#pragma unroll
            for (int half = 0; half < 2; half++) {
                float4 a00 = *(const float4*)(p00 + c0 + 4 * half);
                float4 a01 = *(const float4*)(p01 + c0 + 4 * half);
                float4 a10 = *(const float4*)(p10 + c0 + 4 * half);
                float4 a11 = *(const float4*)(p11 + c0 + 4 * half);
                float v[4];
                v[0] = fmaf(w11, a11.x, fmaf(w10, a10.x, fmaf(w01, a01.x, w00 * a00.x)));
                v[1] = fmaf(w11, a11.y, fmaf(w10, a10.y, fmaf(w01, a01.y, w00 * a00.y)));
                v[2] = fmaf(w11, a11.z, fmaf(w10, a10.z, fmaf(w01, a01.z, w00 * a00.z)));
                v[3] = fmaf(w11, a11.w, fmaf(w10, a10.w, fmaf(w01, a01.w, w00 * a00.w)));
#pragma unroll
                for (int q = 0; q < 2; q++) {
                    uint32_t hp = 0, lp = 0;
#pragma unroll
                    for (int j = 0; j < 2; j++) {
                        float s = v[2 * q + j];
                        __nv_bfloat16 hi = __float2bfloat16(s);
                        __nv_bfloat16 lo = __float2bfloat16(s - __bfloat162float(hi));
                        hp |= ((uint32_t)__bfloat16_as_ushort(hi)) << (16 * j);
                        lp |= ((uint32_t)__bfloat16_as_ushort(lo)) << (16 * j);
                    }
                    Hq[half * 2 + q] = hp;
                    Lq[half * 2 + q] = lp;
                }
            }
            uint32_t so = (uint32_t)(t * 128 + ((cc ^ (t & 7)) * 16));
            *(uint4*)(smb +          so) = make_uint4(Hq[0], Hq[1], Hq[2], Hq[3]);
            *(uint4*)(smb + 16384 + so) = make_uint4(Lq[0], Lq[1], Lq[2], Lq[3]);
        }

        __syncthreads();   // tiles + W ready

        // ---- 3 passes: Shi*Wh, Slo*Wh, Shi*Wl ----
#pragma unroll 1
        for (int pass = 0; pass < 3; pass++) {
            const uint32_t Abase = (pass == 1) ? uAlo : uAhi;
            const int hl = (pass == 2) ? 1 : 0;

            uint32_t afr[2][4][4];
#pragma unroll
            for (int mt = 0; mt < 2; mt++)
#pragma unroll
                for (int kk = 0; kk < 4; kk++)
                    ldm_x4(afr[mt][kk], Abase + lda[mt][kk]);

            const uint2* wf = (const uint2*)sWf + hl * 1024 + lane;
#pragma unroll
            for (int nn = 0; nn < 8; nn++) {
#pragma unroll
                for (int kk = 0; kk < 4; kk++) {
                    uint2 bb = wf[nn * 128 + kk * 32];
                    mma16816(acc + (0 * 8 + nn) * 4, afr[0][kk], &bb.x);
                    mma16816(acc + (1 * 8 + nn) * 4, afr[1][kk], &bb.x);
                }
            }
        }
    }

    // ---- epilogue: D[m][n] -> out[b][n][h*W + m] ----
    float* ob = out + (size_t)b * CC * HWP + h * WW;
#pragma unroll
    for (int mt = 0; mt < 2; mt++) {
        int m = wrp * 32 + mt * 16 + (lane >> 2);
#pragma unroll
        for (int nn = 0; nn < 8; nn++) {
            int n = nn * 8 + 2 * (lane & 3);
            const float* a = acc + (mt * 8 + nn) * 4;
            ob[(size_t)n * HWP + m]           = a[0];
            ob[(size_t)(n + 1) * HWP + m]     = a[1];
            ob[(size_t)n * HWP + m + 8]       = a[2];
            ob[(size_t)(n + 1) * HWP + m + 8] = a[3];
        }
    }
}

// ---------------------------------------------------------------------------
extern "C" void kernel_launch(void* const* d_in, const int* in_sizes, int n_in,
                              void* d_out, int out_size)
{
    const float* x      = (const float*)d_in[0];
    const float* w_conv = (const float*)d_in[1];
    const float* w_off  = (const float*)d_in[2];
    const float* w_msk  = (const float*)d_in[3];

    static bool attr_set = false;
    if (!attr_set) {
        cudaFuncSetAttribute(deform_kernel,
                             cudaFuncAttributeMaxDynamicSharedMemorySize,
                             SMEM_BYTES);
        attr_set = true;
    }

    nhwc_kernel<<<dim3(HWP / 32, CC / 32, BB), dim3(32, 8)>>>(x);
    wfrag_kernel<<<(K2 * 2 * 8 * 4 * 32 + 255) / 256, 256>>>(w_conv);
    offmask_kernel<<<dim3(HH, BB), 128>>>(w_off, w_msk);
    deform_kernel<<<dim3(HH, BB), 128, SMEM_BYTES>>>((float*)d_out);
}

// round 6
// speedup vs baseline: 1.4637x; 1.4637x over previous
#include <cuda_runtime.h>
#include <cuda_bf16.h>
#include <cstdint>

#define BB 8
#define CC 64
#define HH 128
#define WW 128
#define HWP (HH*WW)
#define K2 9
#define OFFC 18
#define MASKC 9
#define NOUT 27
#define NOUTP 28

// ---------------------------------------------------------------------------
// Device scratch (graph-safe)
// ---------------------------------------------------------------------------
__device__ float g_offset[BB * OFFC * HWP];
__device__ float g_mask  [BB * MASKC * HWP];
__device__ float g_xt    [(size_t)BB * HWP * CC];   // x in NHWC (33.5 MB)
// W in mma-fragment order: [tap][hi/lo][nn(8)][kk(4)][lane(32)] x uint2
__device__ __align__(16) uint2 g_wfrag[K2 * 2 * 8 * 4 * 32];

__device__ __forceinline__ uint32_t smem_u32(const void* p) {
    uint32_t a;
    asm("{ .reg .u64 t; cvta.to.shared.u64 t, %1; cvt.u32.u64 %0, t; }" : "=r"(a) : "l"(p));
    return a;
}

__device__ __forceinline__ void ldm_x4(uint32_t* r, uint32_t addr) {
    asm volatile("ldmatrix.sync.aligned.m8n8.x4.shared.b16 {%0,%1,%2,%3}, [%4];"
        : "=r"(r[0]), "=r"(r[1]), "=r"(r[2]), "=r"(r[3]) : "r"(addr));
}

__device__ __forceinline__ void mma16816(float* d, const uint32_t* a, const uint32_t* b) {
    asm volatile(
        "mma.sync.aligned.m16n8k16.row.col.f32.bf16.bf16.f32 "
        "{%0,%1,%2,%3}, {%4,%5,%6,%7}, {%8,%9}, {%0,%1,%2,%3};"
        : "+f"(d[0]), "+f"(d[1]), "+f"(d[2]), "+f"(d[3])
        : "r"(a[0]), "r"(a[1]), "r"(a[2]), "r"(a[3]), "r"(b[0]), "r"(b[1]));
}

// ---------------------------------------------------------------------------
// NCHW -> NHWC transpose via smem tiles
// ---------------------------------------------------------------------------
__global__ __launch_bounds__(256) void nhwc_kernel(const float* __restrict__ x)
{
    __shared__ float tile[32][33];
    const int b  = blockIdx.z;
    const int c0 = blockIdx.y * 32;
    const int p0 = blockIdx.x * 32;
    const int tx = threadIdx.x, ty = threadIdx.y;

#pragma unroll
    for (int i = 0; i < 4; i++)
        tile[ty + 8 * i][tx] = x[((size_t)b * CC + c0 + ty + 8 * i) * HWP + p0 + tx];
    __syncthreads();
#pragma unroll
    for (int i = 0; i < 4; i++)
        g_xt[((size_t)b * HWP + p0 + ty + 8 * i) * CC + c0 + tx] = tile[tx][ty + 8 * i];
}

// ---------------------------------------------------------------------------
// Setup: w_conv [co][c][k] -> fragment-ordered bf16 hi/lo tiles
// ---------------------------------------------------------------------------
__global__ void wfrag_kernel(const float* __restrict__ w_conv)
{
    int i = blockIdx.x * 256 + threadIdx.x;
    if (i >= K2 * 2 * 8 * 4 * 32) return;
    int lane = i & 31;
    int kk   = (i >> 5) & 3;
    int nn   = (i >> 7) & 7;
    int hl   = (i >> 10) & 1;
    int k    = i >> 11;

    int co    = nn * 8 + (lane >> 2);
    int cbase = kk * 16 + 2 * (lane & 3);

    uint32_t regs[2];
#pragma unroll
    for (int r = 0; r < 2; r++) {
        uint32_t pk = 0;
#pragma unroll
        for (int j = 0; j < 2; j++) {
            int c = cbase + r * 8 + j;
            float wv = w_conv[(co * CC + c) * K2 + k];
            __nv_bfloat16 hi = __float2bfloat16(wv);
            float lov = wv - __bfloat162float(hi);
            __nv_bfloat16 v = hl ? __float2bfloat16(lov) : hi;
            pk |= ((uint32_t)__bfloat16_as_ushort(v)) << (16 * j);
        }
        regs[r] = pk;
    }
    g_wfrag[i] = make_uint2(regs[0], regs[1]);
}

// ---------------------------------------------------------------------------
// Kernel 1: offset/mask 3x3 conv — NCHW direct-x version (coalesced stencil)
// ---------------------------------------------------------------------------
__global__ __launch_bounds__(128) void offmask_kernel(
    const float* __restrict__ x,
    const float* __restrict__ w_off,
    const float* __restrict__ w_msk)
{
    const int w = threadIdx.x;
    const int h = blockIdx.x;
    const int b = blockIdx.y;

    __shared__ float ws[16 * 9 * NOUTP];

    float acc[NOUTP];
#pragma unroll
    for (int i = 0; i < NOUTP; i++) acc[i] = 0.f;

    for (int c0 = 0; c0 < CC; c0 += 16) {
        __syncthreads();
        for (int i = threadIdx.x; i < 16 * 9 * NOUTP; i += 128) {
            int co  = i % NOUTP;
            int r   = i / NOUTP;
            int tap = r % 9;
            int cc  = r / 9;
            int c   = c0 + cc;
            float v = 0.f;
            if (co < OFFC)      v = w_off[(co * CC + c) * 9 + tap];
            else if (co < NOUT) v = w_msk[((co - OFFC) * CC + c) * 9 + tap];
            ws[i] = v;
        }
        __syncthreads();

#pragma unroll 1
        for (int cc = 0; cc < 16; cc++) {
            const float* xc = x + (size_t)((b * CC + c0 + cc)) * HWP;
            float xv[9];
#pragma unroll
            for (int dy = 0; dy < 3; dy++) {
                int yy = h + dy - 1;
                bool yok = (yy >= 0) && (yy < HH);
#pragma unroll
                for (int dx = 0; dx < 3; dx++) {
                    int xx = w + dx - 1;
                    bool ok = yok && (xx >= 0) && (xx < WW);
                    xv[dy * 3 + dx] = ok ? __ldg(xc + yy * WW + xx) : 0.f;
                }
            }
#pragma unroll
            for (int tap = 0; tap < 9; tap++) {
                float v = xv[tap];
                const float4* wr = (const float4*)(ws + (cc * 9 + tap) * NOUTP);
#pragma unroll
                for (int q = 0; q < 7; q++) {
                    float4 wv = wr[q];
                    acc[4 * q + 0] = fmaf(wv.x, v, acc[4 * q + 0]);
                    acc[4 * q + 1] = fmaf(wv.y, v, acc[4 * q + 1]);
                    acc[4 * q + 2] = fmaf(wv.z, v, acc[4 * q + 2]);
                    acc[4 * q + 3] = fmaf(wv.w, v, acc[4 * q + 3]);
                }
            }
        }
    }

    const int pix = h * WW + w;
#pragma unroll
    for (int co = 0; co < OFFC; co++)
        g_offset[(b * OFFC + co) * HWP + pix] = acc[co];
#pragma unroll
    for (int cm = 0; cm < MASKC; cm++) {
        float v = acc[OFFC + cm];
        g_mask[(b * MASKC + cm) * HWP + pix] = 1.f / (1.f + __expf(-v));
    }
}

// ---------------------------------------------------------------------------
// Kernel 2: deform via mma.sync; WARP-COOPERATIVE NHWC gather:
// warp w owns pixels [32w,32w+32); for each pixel, lane l loads channels
// {2l,2l+1} (float2) of the 4 corners -> every LDG.64 is a 256B coalesced row.
// ---------------------------------------------------------------------------
#define SM_IDX_OFF 49152                     // bytes: int4 sIdx[128]
#define SM_WT_OFF  (49152 + 2048)            // bytes: float4 sWt[128]
#define SMEM_BYTES (49152 + 4096 + 1024)

__global__ __launch_bounds__(128) void deform_kernel(float* __restrict__ out)
{
    extern __shared__ char smraw[];
    const uint32_t raw_u  = smem_u32(smraw);
    const uint32_t base_u = (raw_u + 1023) & ~1023u;
    char* const smb = smraw + (base_u - raw_u);

    const uint32_t uAhi = base_u;            // 16 KB: [128 pix][64 c] bf16, SW128
    const uint32_t uAlo = base_u + 16384;    // 16 KB
    char* const sWf  = smb + 32768;          // 16 KB: fragment-ordered W (hi+lo)
    int4*   const sIdx = (int4*)(smb + SM_IDX_OFF);
    float4* const sWt  = (float4*)(smb + SM_WT_OFF);

    const int t    = threadIdx.x;
    const int lane = t & 31;
    const int wrp  = t >> 5;
    const int h    = blockIdx.x;
    const int b    = blockIdx.y;

    float acc[64];   // [mt(2)][nn(8)][q(4)]
#pragma unroll
    for (int i = 0; i < 64; i++) acc[i] = 0.f;

    const float* xb = g_xt + (size_t)b * HWP * CC;

    uint32_t lda[2][4];
#pragma unroll
    for (int mt = 0; mt < 2; mt++) {
        int r = wrp * 32 + mt * 16 + (lane & 15);
#pragma unroll
        for (int kk = 0; kk < 4; kk++) {
            int chunk = kk * 2 + (lane >> 4);
            lda[mt][kk] = (uint32_t)(r * 128 + ((chunk ^ (r & 7)) * 16));
        }
    }

    // swizzled 4-byte store slot for this lane within a row (col bytes 4*lane)
    const uint32_t lane_chunk = lane >> 2;
    const uint32_t lane_rem   = (lane & 3) << 2;

#pragma unroll 1
    for (int k = 0; k < K2; k++) {
        __syncthreads();   // previous tap's W reads done

        // ---- stage W fragments for this tap (16 KB) ----
        {
            const uint4* src = (const uint4*)(g_wfrag + (size_t)k * 2048);
            uint4* dst = (uint4*)sWf;
#pragma unroll
            for (int i = 0; i < 8; i++)
                dst[t + 128 * i] = src[t + 128 * i];
        }

        // ---- bilinear params for own pixel -> smem (warp-local consumption) ----
        {
            const int w   = t;
            const int pix = h * WW + w;
            float offy = g_offset[(b * OFFC + 2 * k    ) * HWP + pix];
            float offx = g_offset[(b * OFFC + 2 * k + 1) * HWP + pix];
            float m    = g_mask  [(b * MASKC + k       ) * HWP + pix];

            const int ki = k / 3, kj = k % 3;
            float py = (float)(h + ki - 1) + offy;
            float px = (float)(w + kj - 1) + offx;
            float y0f = floorf(py), x0f = floorf(px);
            int   y0 = (int)y0f,    x0 = (int)x0f;
            int   y1 = y0 + 1,      x1 = x0 + 1;
            float wy1 = py - y0f,   wx1 = px - x0f;
            float wy0 = 1.f - wy1,  wx0 = 1.f - wx1;

            bool vy0 = (y0 >= 0) && (y0 < HH), vy1 = (y1 >= 0) && (y1 < HH);
            bool vx0 = (x0 >= 0) && (x0 < WW), vx1 = (x1 >= 0) && (x1 < WW);

            float w00 = (vy0 && vx0) ? wy0 * wx0 * m : 0.f;
            float w01 = (vy0 && vx1) ? wy0 * wx1 * m : 0.f;
            float w10 = (vy1 && vx0) ? wy1 * wx0 * m : 0.f;
            float w11 = (vy1 && vx1) ? wy1 * wx1 * m : 0.f;

            int yc0 = min(max(y0, 0), HH - 1), yc1 = min(max(y1, 0), HH - 1);
            int xc0 = min(max(x0, 0), WW - 1), xc1 = min(max(x1, 0), WW - 1);

            sIdx[t] = make_int4(yc0 * WW + xc0, yc0 * WW + xc1,
                                yc1 * WW + xc0, yc1 * WW + xc1);
            sWt[t]  = make_float4(w00, w01, w10, w11);
        }
        __syncthreads();   // W + params ready

        // ---- warp-cooperative sampling: 32 pixels, lane covers ch {2l,2l+1} ----
#pragma unroll 4
        for (int pi = 0; pi < 32; pi++) {
            const int p = wrp * 32 + pi;
            int4   idx = sIdx[p];   // broadcast LDS
            float4 wt  = sWt[p];

            const float* c00 = xb + (size_t)idx.x * CC + 2 * lane;
            const float* c01 = xb + (size_t)idx.y * CC + 2 * lane;
            const float* c10 = xb + (size_t)idx.z * CC + 2 * lane;
            const float* c11 = xb + (size_t)idx.w * CC + 2 * lane;
            float2 a00 = *(const float2*)c00;
            float2 a01 = *(const float2*)c01;
            float2 a10 = *(const float2*)c10;
            float2 a11 = *(const float2*)c11;

            float s0 = fmaf(wt.w, a11.x, fmaf(wt.z, a10.x, fmaf(wt.y, a01.x, wt.x * a00.x)));
            float s1 = fmaf(wt.w, a11.y, fmaf(wt.z, a10.y, fmaf(wt.y, a01.y, wt.x * a00.y)));

            __nv_bfloat16 h0 = __float2bfloat16(s0);
            __nv_bfloat16 h1 = __float2bfloat16(s1);
            __nv_bfloat16 l0 = __float2bfloat16(s0 - __bfloat162float(h0));
            __nv_bfloat16 l1 = __float2bfloat16(s1 - __bfloat162float(h1));
            uint32_t hp = (uint32_t)__bfloat16_as_ushort(h0)
                        | ((uint32_t)__bfloat16_as_ushort(h1) << 16);
            uint32_t lp = (uint32_t)__bfloat16_as_ushort(l0)
                        | ((uint32_t)__bfloat16_as_ushort(l1) << 16);

            uint32_t so = (uint32_t)(p * 128)
                        + (((lane_chunk ^ (uint32_t)(p & 7)) << 4) | lane_rem);
            *(uint32_t*)(smb +          so) = hp;
            *(uint32_t*)(smb + 16384 + so) = lp;
        }
        // A-tile rows, params, and mma A-fragments are warp-private: no block
        // sync needed between sampling and mma.

        // ---- 3 passes: Shi*Wh, Slo*Wh, Shi*Wl ----
#pragma unroll 1
        for (int pass = 0; pass < 3; pass++) {
            const uint32_t Abase = (pass == 1) ? uAlo : uAhi;
            const int hl = (pass == 2) ? 1 : 0;

            uint32_t afr[2][4][4];
#pragma unroll
            for (int mt = 0; mt < 2; mt++)
#pragma unroll
                for (int kk = 0; kk < 4; kk++)
                    ldm_x4(afr[mt][kk], Abase + lda[mt][kk]);

            const uint2* wf = (const uint2*)sWf + hl * 1024 + lane;
#pragma unroll
            for (int nn = 0; nn < 8; nn++) {
#pragma unroll
                for (int kk = 0; kk < 4; kk++) {
                    uint2 bb = wf[nn * 128 + kk * 32];
                    mma16816(acc + (0 * 8 + nn) * 4, afr[0][kk], &bb.x);
                    mma16816(acc + (1 * 8 + nn) * 4, afr[1][kk], &bb.x);
                }
            }
        }
    }

    // ---- epilogue: D[m][n] -> out[b][n][h*W + m] ----
    float* ob = out + (size_t)b * CC * HWP + h * WW;
#pragma unroll
    for (int mt = 0; mt < 2; mt++) {
        int m = wrp * 32 + mt * 16 + (lane >> 2);
#pragma unroll
        for (int nn = 0; nn < 8; nn++) {
            int n = nn * 8 + 2 * (lane & 3);
            const float* a = acc + (mt * 8 + nn) * 4;
            ob[(size_t)n * HWP + m]           = a[0];
            ob[(size_t)(n + 1) * HWP + m]     = a[1];
            ob[(size_t)n * HWP + m + 8]       = a[2];
            ob[(size_t)(n + 1) * HWP + m + 8] = a[3];
        }
    }
}

// ---------------------------------------------------------------------------
extern "C" void kernel_launch(void* const* d_in, const int* in_sizes, int n_in,
                              void* d_out, int out_size)
{
    const float* x      = (const float*)d_in[0];
    const float* w_conv = (const float*)d_in[1];
    const float* w_off  = (const float*)d_in[2];
    const float* w_msk  = (const float*)d_in[3];

    static bool attr_set = false;
    if (!attr_set) {
        cudaFuncSetAttribute(deform_kernel,
                             cudaFuncAttributeMaxDynamicSharedMemorySize,
                             SMEM_BYTES);
        attr_set = true;
    }

    nhwc_kernel<<<dim3(HWP / 32, CC / 32, BB), dim3(32, 8)>>>(x);
    wfrag_kernel<<<(K2 * 2 * 8 * 4 * 32 + 255) / 256, 256>>>(w_conv);
    offmask_kernel<<<dim3(HH, BB), 128>>>(x, w_off, w_msk);
    deform_kernel<<<dim3(HH, BB), 128, SMEM_BYTES>>>((float*)d_out);
}

// round 7
// speedup vs baseline: 1.7930x; 1.2250x over previous
#include <cuda_runtime.h>
#include <cuda_bf16.h>
#include <cstdint>

#define BB 8
#define CC 64
#define HH 128
#define WW 128
#define HWP (HH*WW)
#define K2 9
#define OFFC 18
#define MASKC 9
#define NOUT 27

// ---------------------------------------------------------------------------
// Device scratch (graph-safe)
// ---------------------------------------------------------------------------
__device__ float g_offset[BB * OFFC * HWP];
__device__ float g_mask  [BB * MASKC * HWP];
__device__ float g_xt    [(size_t)BB * HWP * CC];   // x in NHWC (33.5 MB)
// deform W fragments: [tap][hi/lo][nn(8)][kk(4)][lane(32)] x uint2
__device__ __align__(16) uint2 g_wfrag[K2 * 2 * 8 * 4 * 32];
// offset/mask W fragments (N padded 27->32): [tap][hi/lo][nn(4)][kk(4)][lane(32)]
__device__ __align__(16) uint2 g_ofrag[K2 * 2 * 4 * 4 * 32];

__device__ __forceinline__ uint32_t smem_u32(const void* p) {
    uint32_t a;
    asm("{ .reg .u64 t; cvta.to.shared.u64 t, %1; cvt.u32.u64 %0, t; }" : "=r"(a) : "l"(p));
    return a;
}

__device__ __forceinline__ void ldm_x4(uint32_t* r, uint32_t addr) {
    asm volatile("ldmatrix.sync.aligned.m8n8.x4.shared.b16 {%0,%1,%2,%3}, [%4];"
        : "=r"(r[0]), "=r"(r[1]), "=r"(r[2]), "=r"(r[3]) : "r"(addr));
}

__device__ __forceinline__ void mma16816(float* d, const uint32_t* a, const uint32_t* b) {
    asm volatile(
        "mma.sync.aligned.m16n8k16.row.col.f32.bf16.bf16.f32 "
        "{%0,%1,%2,%3}, {%4,%5,%6,%7}, {%8,%9}, {%0,%1,%2,%3};"
        : "+f"(d[0]), "+f"(d[1]), "+f"(d[2]), "+f"(d[3])
        : "r"(a[0]), "r"(a[1]), "r"(a[2]), "r"(a[3]), "r"(b[0]), "r"(b[1]));
}

__device__ __forceinline__ void split_pack(float s0, float s1,
                                           uint32_t& hp, uint32_t& lp) {
    __nv_bfloat16 h0 = __float2bfloat16(s0);
    __nv_bfloat16 h1 = __float2bfloat16(s1);
    __nv_bfloat16 l0 = __float2bfloat16(s0 - __bfloat162float(h0));
    __nv_bfloat16 l1 = __float2bfloat16(s1 - __bfloat162float(h1));
    hp = (uint32_t)__bfloat16_as_ushort(h0) | ((uint32_t)__bfloat16_as_ushort(h1) << 16);
    lp = (uint32_t)__bfloat16_as_ushort(l0) | ((uint32_t)__bfloat16_as_ushort(l1) << 16);
}

// ---------------------------------------------------------------------------
// NCHW -> NHWC transpose via smem tiles
// ---------------------------------------------------------------------------
__global__ __launch_bounds__(256) void nhwc_kernel(const float* __restrict__ x)
{
    __shared__ float tile[32][33];
    const int b  = blockIdx.z;
    const int c0 = blockIdx.y * 32;
    const int p0 = blockIdx.x * 32;
    const int tx = threadIdx.x, ty = threadIdx.y;

#pragma unroll
    for (int i = 0; i < 4; i++)
        tile[ty + 8 * i][tx] = x[((size_t)b * CC + c0 + ty + 8 * i) * HWP + p0 + tx];
    __syncthreads();
#pragma unroll
    for (int i = 0; i < 4; i++)
        g_xt[((size_t)b * HWP + p0 + ty + 8 * i) * CC + c0 + tx] = tile[tx][ty + 8 * i];
}

// ---------------------------------------------------------------------------
// Setup: w_conv fragments (deform)
// ---------------------------------------------------------------------------
__global__ void wfrag_kernel(const float* __restrict__ w_conv)
{
    int i = blockIdx.x * 256 + threadIdx.x;
    if (i >= K2 * 2 * 8 * 4 * 32) return;
    int lane = i & 31;
    int kk   = (i >> 5) & 3;
    int nn   = (i >> 7) & 7;
    int hl   = (i >> 10) & 1;
    int k    = i >> 11;

    int co    = nn * 8 + (lane >> 2);
    int cbase = kk * 16 + 2 * (lane & 3);

    uint32_t regs[2];
#pragma unroll
    for (int r = 0; r < 2; r++) {
        uint32_t pk = 0;
#pragma unroll
        for (int j = 0; j < 2; j++) {
            int c = cbase + r * 8 + j;
            float wv = w_conv[(co * CC + c) * K2 + k];
            __nv_bfloat16 hi = __float2bfloat16(wv);
            float lov = wv - __bfloat162float(hi);
            __nv_bfloat16 v = hl ? __float2bfloat16(lov) : hi;
            pk |= ((uint32_t)__bfloat16_as_ushort(v)) << (16 * j);
        }
        regs[r] = pk;
    }
    g_wfrag[i] = make_uint2(regs[0], regs[1]);
}

// ---------------------------------------------------------------------------
// Setup: offset+mask weight fragments, N padded to 32 (rows 27..31 zero)
// ---------------------------------------------------------------------------
__global__ void ofrag_kernel(const float* __restrict__ w_off,
                             const float* __restrict__ w_msk)
{
    int i = blockIdx.x * 256 + threadIdx.x;
    if (i >= K2 * 2 * 4 * 4 * 32) return;
    int lane = i & 31;
    int kk   = (i >> 5) & 3;
    int nn   = (i >> 7) & 3;
    int hl   = (i >> 9) & 1;
    int k    = i >> 10;

    int co    = nn * 8 + (lane >> 2);
    int cbase = kk * 16 + 2 * (lane & 3);

    uint32_t regs[2];
#pragma unroll
    for (int r = 0; r < 2; r++) {
        uint32_t pk = 0;
#pragma unroll
        for (int j = 0; j < 2; j++) {
            int c = cbase + r * 8 + j;
            float wv = 0.f;
            if (co < OFFC)      wv = w_off[(co * CC + c) * K2 + k];
            else if (co < NOUT) wv = w_msk[((co - OFFC) * CC + c) * K2 + k];
            __nv_bfloat16 hi = __float2bfloat16(wv);
            float lov = wv - __bfloat162float(hi);
            __nv_bfloat16 v = hl ? __float2bfloat16(lov) : hi;
            pk |= ((uint32_t)__bfloat16_as_ushort(v)) << (16 * j);
        }
        regs[r] = pk;
    }
    g_ofrag[i] = make_uint2(regs[0], regs[1]);
}

// ---------------------------------------------------------------------------
// Kernel 1: offset/mask conv via mma.sync (bf16 hi/lo), NHWC gather.
// Block = one (b,h) row, 4 warps; D[128 px x 32 ch] accumulated over 9 taps.
// ---------------------------------------------------------------------------
#define OM_SMEM (16384 * 2 + 8192 + 1024)

__global__ __launch_bounds__(128) void offmask_kernel()
{
    extern __shared__ char smraw[];
    const uint32_t raw_u  = smem_u32(smraw);
    const uint32_t base_u = (raw_u + 1023) & ~1023u;
    char* const smb = smraw + (base_u - raw_u);

    const uint32_t uAhi = base_u;            // 16 KB
    const uint32_t uAlo = base_u + 16384;    // 16 KB
    char* const sWf = smb + 32768;           //  8 KB

    const int t    = threadIdx.x;
    const int lane = t & 31;
    const int wrp  = t >> 5;
    const int h    = blockIdx.x;
    const int b    = blockIdx.y;

    float acc[32];   // [mt(2)][nn(4)][q(4)]
#pragma unroll
    for (int i = 0; i < 32; i++) acc[i] = 0.f;

    const float* xb = g_xt + (size_t)b * HWP * CC;

    uint32_t lda[2][4];
#pragma unroll
    for (int mt = 0; mt < 2; mt++) {
        int r = wrp * 32 + mt * 16 + (lane & 15);
#pragma unroll
        for (int kk = 0; kk < 4; kk++) {
            int chunk = kk * 2 + (lane >> 4);
            lda[mt][kk] = (uint32_t)(r * 128 + ((chunk ^ (r & 7)) * 16));
        }
    }
    const uint32_t lane_chunk = lane >> 2;
    const uint32_t lane_rem   = (lane & 3) << 2;

#pragma unroll 1
    for (int k = 0; k < K2; k++) {
        __syncthreads();   // prior tap's Wf reads done

        // stage Wf (8 KB)
        {
            const uint4* src = (const uint4*)(g_ofrag + (size_t)k * 1024);
            uint4* dst = (uint4*)sWf;
#pragma unroll
            for (int i = 0; i < 4; i++)
                dst[t + 128 * i] = src[t + 128 * i];
        }
        __syncthreads();   // Wf ready

        // gather shifted row: warp covers its 32 pixels, lane loads ch {2l,2l+1}
        const int ki = k / 3, kj = k % 3;
        const int yy = h + ki - 1;
        const bool yok = (yy >= 0) && (yy < HH);
#pragma unroll 4
        for (int pi = 0; pi < 32; pi++) {
            const int p  = wrp * 32 + pi;
            const int xx = p + kj - 1;
            float2 a = make_float2(0.f, 0.f);
            if (yok && xx >= 0 && xx < WW)
                a = *(const float2*)(xb + (size_t)(yy * WW + xx) * CC + 2 * lane);
            uint32_t hp, lp;
            split_pack(a.x, a.y, hp, lp);
            uint32_t so = (uint32_t)(p * 128)
                        + (((lane_chunk ^ (uint32_t)(p & 7)) << 4) | lane_rem);
            *(uint32_t*)(smb +          so) = hp;
            *(uint32_t*)(smb + 16384 + so) = lp;
        }
        // A tiles warp-private: no block sync needed before mma

#pragma unroll 1
        for (int pass = 0; pass < 3; pass++) {
            const uint32_t Abase = (pass == 1) ? uAlo : uAhi;
            const int hl = (pass == 2) ? 1 : 0;

            uint32_t afr[2][4][4];
#pragma unroll
            for (int mt = 0; mt < 2; mt++)
#pragma unroll
                for (int kk = 0; kk < 4; kk++)
                    ldm_x4(afr[mt][kk], Abase + lda[mt][kk]);

            const uint2* wf = (const uint2*)sWf + hl * 512 + lane;
#pragma unroll
            for (int nn = 0; nn < 4; nn++) {
#pragma unroll
                for (int kk = 0; kk < 4; kk++) {
                    uint2 bb = wf[nn * 128 + kk * 32];
                    mma16816(acc + (0 * 4 + nn) * 4, afr[0][kk], &bb.x);
                    mma16816(acc + (1 * 4 + nn) * 4, afr[1][kk], &bb.x);
                }
            }
        }
    }

    // epilogue: sigmoid on mask channels; scatter to NCHW offset/mask maps
#pragma unroll
    for (int mt = 0; mt < 2; mt++) {
        int m = wrp * 32 + mt * 16 + (lane >> 2);
#pragma unroll
        for (int nn = 0; nn < 4; nn++) {
            int n = nn * 8 + 2 * (lane & 3);
            const float* a = acc + (mt * 4 + nn) * 4;
#pragma unroll
            for (int q = 0; q < 4; q++) {
                int ch = n + (q & 1);
                int mm = m + (q >> 1) * 8;
                float v = a[q];
                int pix = h * WW + mm;
                if (ch < OFFC)
                    g_offset[(b * OFFC + ch) * HWP + pix] = v;
                else if (ch < NOUT)
                    g_mask[(b * MASKC + ch - OFFC) * HWP + pix] =
                        1.f / (1.f + __expf(-v));
            }
        }
    }
}

// ---------------------------------------------------------------------------
// Kernel 2: deform via mma.sync (unchanged from round 6)
// ---------------------------------------------------------------------------
#define SM_IDX_OFF 49152
#define SM_WT_OFF  (49152 + 2048)
#define SMEM_BYTES (49152 + 4096 + 1024)

__global__ __launch_bounds__(128) void deform_kernel(float* __restrict__ out)
{
    extern __shared__ char smraw[];
    const uint32_t raw_u  = smem_u32(smraw);
    const uint32_t base_u = (raw_u + 1023) & ~1023u;
    char* const smb = smraw + (base_u - raw_u);

    const uint32_t uAhi = base_u;
    const uint32_t uAlo = base_u + 16384;
    char* const sWf  = smb + 32768;
    int4*   const sIdx = (int4*)(smb + SM_IDX_OFF);
    float4* const sWt  = (float4*)(smb + SM_WT_OFF);

    const int t    = threadIdx.x;
    const int lane = t & 31;
    const int wrp  = t >> 5;
    const int h    = blockIdx.x;
    const int b    = blockIdx.y;

    float acc[64];
#pragma unroll
    for (int i = 0; i < 64; i++) acc[i] = 0.f;

    const float* xb = g_xt + (size_t)b * HWP * CC;

    uint32_t lda[2][4];
#pragma unroll
    for (int mt = 0; mt < 2; mt++) {
        int r = wrp * 32 + mt * 16 + (lane & 15);
#pragma unroll
        for (int kk = 0; kk < 4; kk++) {
            int chunk = kk * 2 + (lane >> 4);
            lda[mt][kk] = (uint32_t)(r * 128 + ((chunk ^ (r & 7)) * 16));
        }
    }
    const uint32_t lane_chunk = lane >> 2;
    const uint32_t lane_rem   = (lane & 3) << 2;

#pragma unroll 1
    for (int k = 0; k < K2; k++) {
        __syncthreads();

        {
            const uint4* src = (const uint4*)(g_wfrag + (size_t)k * 2048);
            uint4* dst = (uint4*)sWf;
#pragma unroll
            for (int i = 0; i < 8; i++)
                dst[t + 128 * i] = src[t + 128 * i];
        }

        {
            const int w   = t;
            const int pix = h * WW + w;
            float offy = g_offset[(b * OFFC + 2 * k    ) * HWP + pix];
            float offx = g_offset[(b * OFFC + 2 * k + 1) * HWP + pix];
            float m    = g_mask  [(b * MASKC + k       ) * HWP + pix];

            const int ki = k / 3, kj = k % 3;
            float py = (float)(h + ki - 1) + offy;
            float px = (float)(w + kj - 1) + offx;
            float y0f = floorf(py), x0f = floorf(px);
            int   y0 = (int)y0f,    x0 = (int)x0f;
            int   y1 = y0 + 1,      x1 = x0 + 1;
            float wy1 = py - y0f,   wx1 = px - x0f;
            float wy0 = 1.f - wy1,  wx0 = 1.f - wx1;

            bool vy0 = (y0 >= 0) && (y0 < HH), vy1 = (y1 >= 0) && (y1 < HH);
            bool vx0 = (x0 >= 0) && (x0 < WW), vx1 = (x1 >= 0) && (x1 < WW);

            float w00 = (vy0 && vx0) ? wy0 * wx0 * m : 0.f;
            float w01 = (vy0 && vx1) ? wy0 * wx1 * m : 0.f;
            float w10 = (vy1 && vx0) ? wy1 * wx0 * m : 0.f;
            float w11 = (vy1 && vx1) ? wy1 * wx1 * m : 0.f;

            int yc0 = min(max(y0, 0), HH - 1), yc1 = min(max(y1, 0), HH - 1);
            int xc0 = min(max(x0, 0), WW - 1), xc1 = min(max(x1, 0), WW - 1);

            sIdx[t] = make_int4(yc0 * WW + xc0, yc0 * WW + xc1,
                                yc1 * WW + xc0, yc1 * WW + xc1);
            sWt[t]  = make_float4(w00, w01, w10, w11);
        }
        __syncthreads();

#pragma unroll 4
        for (int pi = 0; pi < 32; pi++) {
            const int p = wrp * 32 + pi;
            int4   idx = sIdx[p];
            float4 wt  = sWt[p];

            float2 a00 = *(const float2*)(xb + (size_t)idx.x * CC + 2 * lane);
            float2 a01 = *(const float2*)(xb + (size_t)idx.y * CC + 2 * lane);
            float2 a10 = *(const float2*)(xb + (size_t)idx.z * CC + 2 * lane);
            float2 a11 = *(const float2*)(xb + (size_t)idx.w * CC + 2 * lane);

            float s0 = fmaf(wt.w, a11.x, fmaf(wt.z, a10.x, fmaf(wt.y, a01.x, wt.x * a00.x)));
            float s1 = fmaf(wt.w, a11.y, fmaf(wt.z, a10.y, fmaf(wt.y, a01.y, wt.x * a00.y)));

            uint32_t hp, lp;
            split_pack(s0, s1, hp, lp);
            uint32_t so = (uint32_t)(p * 128)
                        + (((lane_chunk ^ (uint32_t)(p & 7)) << 4) | lane_rem);
            *(uint32_t*)(smb +          so) = hp;
            *(uint32_t*)(smb + 16384 + so) = lp;
        }

#pragma unroll 1
        for (int pass = 0; pass < 3; pass++) {
            const uint32_t Abase = (pass == 1) ? uAlo : uAhi;
            const int hl = (pass == 2) ? 1 : 0;

            uint32_t afr[2][4][4];
#pragma unroll
            for (int mt = 0; mt < 2; mt++)
#pragma unroll
                for (int kk = 0; kk < 4; kk++)
                    ldm_x4(afr[mt][kk], Abase + lda[mt][kk]);

            const uint2* wf = (const uint2*)sWf + hl * 1024 + lane;
#pragma unroll
            for (int nn = 0; nn < 8; nn++) {
#pragma unroll
                for (int kk = 0; kk < 4; kk++) {
                    uint2 bb = wf[nn * 128 + kk * 32];
                    mma16816(acc + (0 * 8 + nn) * 4, afr[0][kk], &bb.x);
                    mma16816(acc + (1 * 8 + nn) * 4, afr[1][kk], &bb.x);
                }
            }
        }
    }

    float* ob = out + (size_t)b * CC * HWP + h * WW;
#pragma unroll
    for (int mt = 0; mt < 2; mt++) {
        int m = wrp * 32 + mt * 16 + (lane >> 2);
#pragma unroll
        for (int nn = 0; nn < 8; nn++) {
            int n = nn * 8 + 2 * (lane & 3);
            const float* a = acc + (mt * 8 + nn) * 4;
            ob[(size_t)n * HWP + m]           = a[0];
            ob[(size_t)(n + 1) * HWP + m]     = a[1];
            ob[(size_t)n * HWP + m + 8]       = a[2];
            ob[(size_t)(n + 1) * HWP + m + 8] = a[3];
        }
    }
}

// ---------------------------------------------------------------------------
extern "C" void kernel_launch(void* const* d_in, const int* in_sizes, int n_in,
                              void* d_out, int out_size)
{
    const float* x      = (const float*)d_in[0];
    const float* w_conv = (const float*)d_in[1];
    const float* w_off  = (const float*)d_in[2];
    const float* w_msk  = (const float*)d_in[3];

    static bool attr_set = false;
    if (!attr_set) {
        cudaFuncSetAttribute(deform_kernel,
                             cudaFuncAttributeMaxDynamicSharedMemorySize,
                             SMEM_BYTES);
        cudaFuncSetAttribute(offmask_kernel,
                             cudaFuncAttributeMaxDynamicSharedMemorySize,
                             OM_SMEM);
        attr_set = true;
    }

    nhwc_kernel<<<dim3(HWP / 32, CC / 32, BB), dim3(32, 8)>>>(x);
    wfrag_kernel<<<(K2 * 2 * 8 * 4 * 32 + 255) / 256, 256>>>(w_conv);
    ofrag_kernel<<<(K2 * 2 * 4 * 4 * 32 + 255) / 256, 256>>>(w_off, w_msk);
    offmask_kernel<<<dim3(HH, BB), 128, OM_SMEM>>>();
    deform_kernel<<<dim3(HH, BB), 128, SMEM_BYTES>>>((float*)d_out);
}

// round 8
// speedup vs baseline: 2.1738x; 1.2124x over previous
#include <cuda_runtime.h>
#include <cuda_bf16.h>
#include <cstdint>

#define BB 8
#define CC 64
#define HH 128
#define WW 128
#define HWP (HH*WW)
#define K2 9
#define OFFC 18
#define MASKC 9
#define NOUT 27

// ---------------------------------------------------------------------------
// Device scratch (graph-safe)
// ---------------------------------------------------------------------------
__device__ float g_offset[BB * OFFC * HWP];
__device__ float g_mask  [BB * MASKC * HWP];
__device__ float g_xt    [(size_t)BB * HWP * CC];   // x in NHWC (33.5 MB)
// deform W fragments: [tap][hi/lo][nn(8)][kk(4)][lane(32)] x uint2
__device__ __align__(16) uint2 g_wfrag[K2 * 2 * 8 * 4 * 32];
// offset/mask W fragments (N padded 27->32): [tap][hi/lo][nn(4)][kk(4)][lane(32)]
__device__ __align__(16) uint2 g_ofrag[K2 * 2 * 4 * 4 * 32];

__device__ __forceinline__ uint32_t smem_u32(const void* p) {
    uint32_t a;
    asm("{ .reg .u64 t; cvta.to.shared.u64 t, %1; cvt.u32.u64 %0, t; }" : "=r"(a) : "l"(p));
    return a;
}

__device__ __forceinline__ void ldm_x4(uint32_t* r, uint32_t addr) {
    asm volatile("ldmatrix.sync.aligned.m8n8.x4.shared.b16 {%0,%1,%2,%3}, [%4];"
        : "=r"(r[0]), "=r"(r[1]), "=r"(r[2]), "=r"(r[3]) : "r"(addr));
}

__device__ __forceinline__ void mma16816(float* d, const uint32_t* a, const uint32_t* b) {
    asm volatile(
        "mma.sync.aligned.m16n8k16.row.col.f32.bf16.bf16.f32 "
        "{%0,%1,%2,%3}, {%4,%5,%6,%7}, {%8,%9}, {%0,%1,%2,%3};"
        : "+f"(d[0]), "+f"(d[1]), "+f"(d[2]), "+f"(d[3])
        : "r"(a[0]), "r"(a[1]), "r"(a[2]), "r"(a[3]), "r"(b[0]), "r"(b[1]));
}

__device__ __forceinline__ void split_pack(float s0, float s1,
                                           uint32_t& hp, uint32_t& lp) {
    __nv_bfloat16 h0 = __float2bfloat16(s0);
    __nv_bfloat16 h1 = __float2bfloat16(s1);
    __nv_bfloat16 l0 = __float2bfloat16(s0 - __bfloat162float(h0));
    __nv_bfloat16 l1 = __float2bfloat16(s1 - __bfloat162float(h1));
    hp = (uint32_t)__bfloat16_as_ushort(h0) | ((uint32_t)__bfloat16_as_ushort(h1) << 16);
    lp = (uint32_t)__bfloat16_as_ushort(l0) | ((uint32_t)__bfloat16_as_ushort(l1) << 16);
}

// ---------------------------------------------------------------------------
// NCHW -> NHWC transpose via smem tiles
// ---------------------------------------------------------------------------
__global__ __launch_bounds__(256) void nhwc_kernel(const float* __restrict__ x)
{
    __shared__ float tile[32][33];
    const int b  = blockIdx.z;
    const int c0 = blockIdx.y * 32;
    const int p0 = blockIdx.x * 32;
    const int tx = threadIdx.x, ty = threadIdx.y;

#pragma unroll
    for (int i = 0; i < 4; i++)
        tile[ty + 8 * i][tx] = x[((size_t)b * CC + c0 + ty + 8 * i) * HWP + p0 + tx];
    __syncthreads();
#pragma unroll
    for (int i = 0; i < 4; i++)
        g_xt[((size_t)b * HWP + p0 + ty + 8 * i) * CC + c0 + tx] = tile[tx][ty + 8 * i];
}

// ---------------------------------------------------------------------------
// Setup: w_conv fragments (deform)
// ---------------------------------------------------------------------------
__global__ void wfrag_kernel(const float* __restrict__ w_conv)
{
    int i = blockIdx.x * 256 + threadIdx.x;
    if (i >= K2 * 2 * 8 * 4 * 32) return;
    int lane = i & 31;
    int kk   = (i >> 5) & 3;
    int nn   = (i >> 7) & 7;
    int hl   = (i >> 10) & 1;
    int k    = i >> 11;

    int co    = nn * 8 + (lane >> 2);
    int cbase = kk * 16 + 2 * (lane & 3);

    uint32_t regs[2];
#pragma unroll
    for (int r = 0; r < 2; r++) {
        uint32_t pk = 0;
#pragma unroll
        for (int j = 0; j < 2; j++) {
            int c = cbase + r * 8 + j;
            float wv = w_conv[(co * CC + c) * K2 + k];
            __nv_bfloat16 hi = __float2bfloat16(wv);
            float lov = wv - __bfloat162float(hi);
            __nv_bfloat16 v = hl ? __float2bfloat16(lov) : hi;
            pk |= ((uint32_t)__bfloat16_as_ushort(v)) << (16 * j);
        }
        regs[r] = pk;
    }
    g_wfrag[i] = make_uint2(regs[0], regs[1]);
}

// ---------------------------------------------------------------------------
// Setup: offset+mask weight fragments, N padded to 32 (rows 27..31 zero)
// ---------------------------------------------------------------------------
__global__ void ofrag_kernel(const float* __restrict__ w_off,
                             const float* __restrict__ w_msk)
{
    int i = blockIdx.x * 256 + threadIdx.x;
    if (i >= K2 * 2 * 4 * 4 * 32) return;
    int lane = i & 31;
    int kk   = (i >> 5) & 3;
    int nn   = (i >> 7) & 3;
    int hl   = (i >> 9) & 1;
    int k    = i >> 10;

    int co    = nn * 8 + (lane >> 2);
    int cbase = kk * 16 + 2 * (lane & 3);

    uint32_t regs[2];
#pragma unroll
    for (int r = 0; r < 2; r++) {
        uint32_t pk = 0;
#pragma unroll
        for (int j = 0; j < 2; j++) {
            int c = cbase + r * 8 + j;
            float wv = 0.f;
            if (co < OFFC)      wv = w_off[(co * CC + c) * K2 + k];
            else if (co < NOUT) wv = w_msk[((co - OFFC) * CC + c) * K2 + k];
            __nv_bfloat16 hi = __float2bfloat16(wv);
            float lov = wv - __bfloat162float(hi);
            __nv_bfloat16 v = hl ? __float2bfloat16(lov) : hi;
            pk |= ((uint32_t)__bfloat16_as_ushort(v)) << (16 * j);
        }
        regs[r] = pk;
    }
    g_ofrag[i] = make_uint2(regs[0], regs[1]);
}

// ---------------------------------------------------------------------------
// Kernel 1: offset/mask conv via mma.sync — warp-private 34-px windows.
// Per y-row: gather+split ONCE; 3 x-shifted taps reuse the tile via shifted
// ldmatrix rows. No __syncthreads anywhere; B-fragments direct from global.
// ---------------------------------------------------------------------------
#define OM_WBYTES (2 * 34 * 128)             // hi+lo window per warp (8704 B)
#define OM_SMEM   (4 * OM_WBYTES + 1024)

__global__ __launch_bounds__(128) void offmask_kernel()
{
    extern __shared__ char smraw[];
    const uint32_t raw_u  = smem_u32(smraw);
    const uint32_t base_u = (raw_u + 1023) & ~1023u;
    char* const smb = smraw + (base_u - raw_u);

    const int t    = threadIdx.x;
    const int lane = t & 31;
    const int wrp  = t >> 5;
    const int h    = blockIdx.x;
    const int b    = blockIdx.y;

    char* const wt_hi = smb + wrp * OM_WBYTES;
    char* const wt_lo = wt_hi + 34 * 128;
    const uint32_t uHi = base_u + wrp * OM_WBYTES;
    const uint32_t uLo = uHi + 34 * 128;

    float acc[32];   // [mt(2)][nn(4)][q(4)]
#pragma unroll
    for (int i = 0; i < 32; i++) acc[i] = 0.f;

    const float* xb = g_xt + (size_t)b * HWP * CC;
    const uint32_t lane_chunk = lane >> 2;
    const uint32_t lane_rem   = (lane & 3) << 2;
    const int p0 = wrp * 32 - 1;   // pixel of window row 0

#pragma unroll 1
    for (int ki = 0; ki < 3; ki++) {
        const int yy = h + ki - 1;
        const bool yok = (yy >= 0) && (yy < HH);

        __syncwarp();   // prior taps' ldmatrix reads of this window done
        // ---- gather 34-pixel window once for this y-row ----
#pragma unroll 2
        for (int pi = 0; pi < 34; pi++) {
            const int q = p0 + pi;
            float2 a = make_float2(0.f, 0.f);
            if (yok && q >= 0 && q < WW)
                a = *(const float2*)(xb + (size_t)(yy * WW + q) * CC + 2 * lane);
            uint32_t hp, lp;
            split_pack(a.x, a.y, hp, lp);
            uint32_t so = (uint32_t)(pi * 128)
                        + (((lane_chunk ^ (uint32_t)(pi & 7)) << 4) | lane_rem);
            *(uint32_t*)(wt_hi + so) = hp;
            *(uint32_t*)(wt_lo + so) = lp;
        }
        __syncwarp();

        // ---- 3 x-shifted taps from the same window ----
#pragma unroll 1
        for (int kj = 0; kj < 3; kj++) {
            const int k = ki * 3 + kj;
            const uint2* wfb = g_ofrag + (size_t)k * 1024 + lane;

#pragma unroll 1
            for (int pass = 0; pass < 3; pass++) {
                const uint32_t Abase = (pass == 1) ? uLo : uHi;
                const int hl = (pass == 2) ? 1 : 0;

                uint32_t afr[2][4][4];
#pragma unroll
                for (int mt = 0; mt < 2; mt++) {
                    const int rs = mt * 16 + (lane & 15) + kj;   // shifted row
                    const uint32_t rb = (uint32_t)(rs * 128);
                    const uint32_t r7 = (uint32_t)(rs & 7);
#pragma unroll
                    for (int kk = 0; kk < 4; kk++) {
                        uint32_t chunk = (uint32_t)(kk * 2) + (uint32_t)(lane >> 4);
                        ldm_x4(afr[mt][kk], Abase + rb + ((chunk ^ r7) << 4));
                    }
                }

                const uint2* wf = wfb + hl * 512;
#pragma unroll
                for (int nn = 0; nn < 4; nn++) {
#pragma unroll
                    for (int kk = 0; kk < 4; kk++) {
                        uint2 bb = __ldg(wf + nn * 128 + kk * 32);
                        mma16816(acc + (0 * 4 + nn) * 4, afr[0][kk], &bb.x);
                        mma16816(acc + (1 * 4 + nn) * 4, afr[1][kk], &bb.x);
                    }
                }
            }
        }
    }

    // epilogue: sigmoid on mask channels; scatter to NCHW offset/mask maps
#pragma unroll
    for (int mt = 0; mt < 2; mt++) {
        int m = wrp * 32 + mt * 16 + (lane >> 2);
#pragma unroll
        for (int nn = 0; nn < 4; nn++) {
            int n = nn * 8 + 2 * (lane & 3);
            const float* a = acc + (mt * 4 + nn) * 4;
#pragma unroll
            for (int q = 0; q < 4; q++) {
                int ch = n + (q & 1);
                int mm = m + (q >> 1) * 8;
                float v = a[q];
                int pix = h * WW + mm;
                if (ch < OFFC)
                    g_offset[(b * OFFC + ch) * HWP + pix] = v;
                else if (ch < NOUT)
                    g_mask[(b * MASKC + ch - OFFC) * HWP + pix] =
                        1.f / (1.f + __expf(-v));
            }
        }
    }
}

// ---------------------------------------------------------------------------
// Kernel 2: deform via mma.sync (unchanged — proven at 218 us)
// ---------------------------------------------------------------------------
#define SM_IDX_OFF 49152
#define SM_WT_OFF  (49152 + 2048)
#define SMEM_BYTES (49152 + 4096 + 1024)

__global__ __launch_bounds__(128) void deform_kernel(float* __restrict__ out)
{
    extern __shared__ char smraw[];
    const uint32_t raw_u  = smem_u32(smraw);
    const uint32_t base_u = (raw_u + 1023) & ~1023u;
    char* const smb = smraw + (base_u - raw_u);

    const uint32_t uAhi = base_u;
    const uint32_t uAlo = base_u + 16384;
    char* const sWf  = smb + 32768;
    int4*   const sIdx = (int4*)(smb + SM_IDX_OFF);
    float4* const sWt  = (float4*)(smb + SM_WT_OFF);

    const int t    = threadIdx.x;
    const int lane = t & 31;
    const int wrp  = t >> 5;
    const int h    = blockIdx.x;
    const int b    = blockIdx.y;

    float acc[64];
#pragma unroll
    for (int i = 0; i < 64; i++) acc[i] = 0.f;

    const float* xb = g_xt + (size_t)b * HWP * CC;

    uint32_t lda[2][4];
#pragma unroll
    for (int mt = 0; mt < 2; mt++) {
        int r = wrp * 32 + mt * 16 + (lane & 15);
#pragma unroll
        for (int kk = 0; kk < 4; kk++) {
            int chunk = kk * 2 + (lane >> 4);
            lda[mt][kk] = (uint32_t)(r * 128 + ((chunk ^ (r & 7)) * 16));
        }
    }
    const uint32_t lane_chunk = lane >> 2;
    const uint32_t lane_rem   = (lane & 3) << 2;

#pragma unroll 1
    for (int k = 0; k < K2; k++) {
        __syncthreads();

        {
            const uint4* src = (const uint4*)(g_wfrag + (size_t)k * 2048);
            uint4* dst = (uint4*)sWf;
#pragma unroll
            for (int i = 0; i < 8; i++)
                dst[t + 128 * i] = src[t + 128 * i];
        }

        {
            const int w   = t;
            const int pix = h * WW + w;
            float offy = g_offset[(b * OFFC + 2 * k    ) * HWP + pix];
            float offx = g_offset[(b * OFFC + 2 * k + 1) * HWP + pix];
            float m    = g_mask  [(b * MASKC + k       ) * HWP + pix];

            const int ki = k / 3, kj = k % 3;
            float py = (float)(h + ki - 1) + offy;
            float px = (float)(w + kj - 1) + offx;
            float y0f = floorf(py), x0f = floorf(px);
            int   y0 = (int)y0f,    x0 = (int)x0f;
            int   y1 = y0 + 1,      x1 = x0 + 1;
            float wy1 = py - y0f,   wx1 = px - x0f;
            float wy0 = 1.f - wy1,  wx0 = 1.f - wx1;

            bool vy0 = (y0 >= 0) && (y0 < HH), vy1 = (y1 >= 0) && (y1 < HH);
            bool vx0 = (x0 >= 0) && (x0 < WW), vx1 = (x1 >= 0) && (x1 < WW);

            float w00 = (vy0 && vx0) ? wy0 * wx0 * m : 0.f;
            float w01 = (vy0 && vx1) ? wy0 * wx1 * m : 0.f;
            float w10 = (vy1 && vx0) ? wy1 * wx0 * m : 0.f;
            float w11 = (vy1 && vx1) ? wy1 * wx1 * m : 0.f;

            int yc0 = min(max(y0, 0), HH - 1), yc1 = min(max(y1, 0), HH - 1);
            int xc0 = min(max(x0, 0), WW - 1), xc1 = min(max(x1, 0), WW - 1);

            sIdx[t] = make_int4(yc0 * WW + xc0, yc0 * WW + xc1,
                                yc1 * WW + xc0, yc1 * WW + xc1);
            sWt[t]  = make_float4(w00, w01, w10, w11);
        }
        __syncthreads();

#pragma unroll 4
        for (int pi = 0; pi < 32; pi++) {
            const int p = wrp * 32 + pi;
            int4   idx = sIdx[p];
            float4 wt  = sWt[p];

            float2 a00 = *(const float2*)(xb + (size_t)idx.x * CC + 2 * lane);
            float2 a01 = *(const float2*)(xb + (size_t)idx.y * CC + 2 * lane);
            float2 a10 = *(const float2*)(xb + (size_t)idx.z * CC + 2 * lane);
            float2 a11 = *(const float2*)(xb + (size_t)idx.w * CC + 2 * lane);

            float s0 = fmaf(wt.w, a11.x, fmaf(wt.z, a10.x, fmaf(wt.y, a01.x, wt.x * a00.x)));
            float s1 = fmaf(wt.w, a11.y, fmaf(wt.z, a10.y, fmaf(wt.y, a01.y, wt.x * a00.y)));

            uint32_t hp, lp;
            split_pack(s0, s1, hp, lp);
            uint32_t so = (uint32_t)(p * 128)
                        + (((lane_chunk ^ (uint32_t)(p & 7)) << 4) | lane_rem);
            *(uint32_t*)(smb +          so) = hp;
            *(uint32_t*)(smb + 16384 + so) = lp;
        }

#pragma unroll 1
        for (int pass = 0; pass < 3; pass++) {
            const uint32_t Abase = (pass == 1) ? uAlo : uAhi;
            const int hl = (pass == 2) ? 1 : 0;

            uint32_t afr[2][4][4];
#pragma unroll
            for (int mt = 0; mt < 2; mt++)
#pragma unroll
                for (int kk = 0; kk < 4; kk++)
                    ldm_x4(afr[mt][kk], Abase + lda[mt][kk]);

            const uint2* wf = (const uint2*)sWf + hl * 1024 + lane;
#pragma unroll
            for (int nn = 0; nn < 8; nn++) {
#pragma unroll
                for (int kk = 0; kk < 4; kk++) {
                    uint2 bb = wf[nn * 128 + kk * 32];
                    mma16816(acc + (0 * 8 + nn) * 4, afr[0][kk], &bb.x);
                    mma16816(acc + (1 * 8 + nn) * 4, afr[1][kk], &bb.x);
                }
            }
        }
    }

    float* ob = out + (size_t)b * CC * HWP + h * WW;
#pragma unroll
    for (int mt = 0; mt < 2; mt++) {
        int m = wrp * 32 + mt * 16 + (lane >> 2);
#pragma unroll
        for (int nn = 0; nn < 8; nn++) {
            int n = nn * 8 + 2 * (lane & 3);
            const float* a = acc + (mt * 8 + nn) * 4;
            ob[(size_t)n * HWP + m]           = a[0];
            ob[(size_t)(n + 1) * HWP + m]     = a[1];
            ob[(size_t)n * HWP + m + 8]       = a[2];
            ob[(size_t)(n + 1) * HWP + m + 8] = a[3];
        }
    }
}

// ---------------------------------------------------------------------------
extern "C" void kernel_launch(void* const* d_in, const int* in_sizes, int n_in,
                              void* d_out, int out_size)
{
    const float* x      = (const float*)d_in[0];
    const float* w_conv = (const float*)d_in[1];
    const float* w_off  = (const float*)d_in[2];
    const float* w_msk  = (const float*)d_in[3];

    static bool attr_set = false;
    if (!attr_set) {
        cudaFuncSetAttribute(deform_kernel,
                             cudaFuncAttributeMaxDynamicSharedMemorySize,
                             SMEM_BYTES);
        cudaFuncSetAttribute(offmask_kernel,
                             cudaFuncAttributeMaxDynamicSharedMemorySize,
                             OM_SMEM);
        attr_set = true;
    }

    nhwc_kernel<<<dim3(HWP / 32, CC / 32, BB), dim3(32, 8)>>>(x);
    wfrag_kernel<<<(K2 * 2 * 8 * 4 * 32 + 255) / 256, 256>>>(w_conv);
    ofrag_kernel<<<(K2 * 2 * 4 * 4 * 32 + 255) / 256, 256>>>(w_off, w_msk);
    offmask_kernel<<<dim3(HH, BB), 128, OM_SMEM>>>();
    deform_kernel<<<dim3(HH, BB), 128, SMEM_BYTES>>>((float*)d_out);
}